// round 4
// baseline (speedup 1.0000x reference)
#include <cuda_runtime.h>

// Problem constants (fixed shapes)
constexpr int B  = 16;
constexpr int N  = 4096;
constexpr int K  = 32;
constexpr int BN = B * N;   // 65536

constexpr int BLOCKS_PER_BATCH = 9;
constexpr int THREADS = 256;              // 8 warps
constexpr int CHUNKS_PER_BATCH = N / 32;  // 128 chunks of 32 bn

// Smem layout (dynamic): frame table + per-warp staging
constexpr int TABLE_FLOATS = N * 12;      // 49152 floats = 192KB
constexpr int ROT_STRIDE   = 168;         // per-bn rot half-tile (144 used), %32==8
constexpr int TRN_STRIDE   = 72;          // per-bn trans half-tile (48 used), %32==8
constexpr int WARP_STAGE   = 4 * ROT_STRIDE + 4 * TRN_STRIDE;  // 960 floats
constexpr int SMEM_BYTES   = (TABLE_FLOATS + 8 * WARP_STAGE) * 4;  // 227328 B

// Scratch for avg rigids between kernels
__device__ float g_avg[BN * 12];

// ---------------------------------------------------------------------------
// Kernel 1 (fused repack + compose + average):
// grid = 16 batches x 9 blocks. Each block loads its batch's full frame table
// (4096 x [rot9|trans3]) into shared memory, then processes whole 32-bn chunks:
// 4 bn per warp, 8 lanes per bn, neighbors split into two halves of 16 with
// both halves' streaming GMEM data prefetched into registers up front.
// ---------------------------------------------------------------------------
__global__ __launch_bounds__(THREADS) void compose_avg_kernel(
    const float* __restrict__ frames_rot,
    const float* __restrict__ frames_trans,
    const float* __restrict__ pair_rot,
    const float* __restrict__ pair_trans,
    const float* __restrict__ conf,
    const int*   __restrict__ topo) {

    extern __shared__ float sm[];
    float* table = sm;                         // N*12 floats
    float* stage = sm + TABLE_FLOATS;

    int tid  = threadIdx.x;
    int warp = tid >> 5;
    int lane = tid & 31;
    int g    = lane >> 3;                      // bn tile within warp (0..3)
    int s    = lane & 7;                       // sub-lane within tile (0..7)

    int b = blockIdx.x / BLOCKS_PER_BATCH;
    int r = blockIdx.x - b * BLOCKS_PER_BATCH;

    // --- load batch frame table into smem (vectorized, coalesced) ---
    {
        const float4* fr4 = (const float4*)(frames_rot + (size_t)b * N * 9);
        for (int i = tid; i < N * 9 / 4; i += THREADS) {
            float4 v = fr4[i];
            int e = 4 * i;
#pragma unroll
            for (int u = 0; u < 4; u++) {
                int el = e + u;
                int fi = el / 9, c = el - fi * 9;
                table[fi * 12 + c] = (&v.x)[u];
            }
        }
        const float4* ft4 = (const float4*)(frames_trans + (size_t)b * N * 3);
        for (int i = tid; i < N * 3 / 4; i += THREADS) {
            float4 v = ft4[i];
            int e = 4 * i;
#pragma unroll
            for (int u = 0; u < 4; u++) {
                int el = e + u;
                int fi = el / 3, c = el - fi * 3;
                table[fi * 12 + 9 + c] = (&v.x)[u];
            }
        }
    }
    __syncthreads();

    float* rotbuf = stage + warp * WARP_STAGE;         // 4 x 168 floats
    float* trnbuf = rotbuf + 4 * ROT_STRIDE;           // 4 x 72 floats
    float4* rb4 = (float4*)rotbuf;                     // tile stride 42 float4
    float4* tb4 = (float4*)trnbuf;                     // tile stride 18 float4

    // chunk range for this block (whole chunks, no ragged warps)
    int cbase = r * 14 + (r < 2 ? r : 2);
    int cnum  = 14 + (r < 2 ? 1 : 0);

    const float4* pr4 = (const float4*)pair_rot;
    const float4* pt4 = (const float4*)pair_trans;

    for (int it = 0; it < cnum; it++) {
        int bn0l = (cbase + it) * 32 + warp * 4;       // batch-local base bn
        size_t bn0g = (size_t)b * N + bn0l;            // global base bn
        size_t bng  = bn0g + g;                        // this lane's bn

        // --- conf & topo for this lane's 4 neighbors ---
        const float* cfb = conf + bng * K;
        const int*   tpb = topo + bng * K;
        float wgt[4];
        int   jj[4];
#pragma unroll
        for (int i = 0; i < 4; i++) {
            wgt[i] = cfb[s + 8 * i];
            jj[i]  = tpb[s + 8 * i];
        }

        // --- prefetch BOTH halves of streaming pair data into registers ---
        float4 rreg[2][5];
        float4 treg[2][2];
#pragma unroll
        for (int q = 0; q < 5; q++) {
            int f = q * 32 + lane;                     // 0..159 (144 valid)
            int t = f / 36, w = f - t * 36;
            bool ok = (f < 144);
            size_t base = (bn0g + t) * 72 + w;
            rreg[0][q] = ok ? pr4[base]      : make_float4(0, 0, 0, 0);
            rreg[1][q] = ok ? pr4[base + 36] : make_float4(0, 0, 0, 0);
        }
#pragma unroll
        for (int q = 0; q < 2; q++) {
            int f = q * 32 + lane;                     // 0..63 (48 valid)
            int t = f / 12, w = f - t * 12;
            bool ok = (f < 48);
            size_t base = (bn0g + t) * 24 + w;
            treg[0][q] = ok ? pt4[base]      : make_float4(0, 0, 0, 0);
            treg[1][q] = ok ? pt4[base + 12] : make_float4(0, 0, 0, 0);
        }

        float acc[13];
#pragma unroll
        for (int v = 0; v < 13; v++) acc[v] = 0.0f;

#pragma unroll
        for (int h = 0; h < 2; h++) {
            // --- stage half h to smem ---
#pragma unroll
            for (int q = 0; q < 5; q++) {
                int f = q * 32 + lane;
                if (f < 144) {
                    int t = f / 36, w = f - t * 36;
                    rb4[t * 42 + w] = rreg[h][q];
                }
            }
#pragma unroll
            for (int q = 0; q < 2; q++) {
                int f = q * 32 + lane;
                if (f < 48) {
                    int t = f / 12, w = f - t * 12;
                    tb4[t * 18 + w] = treg[h][q];
                }
            }
            __syncwarp();

            // --- consume: 2 neighbors per lane in this half ---
#pragma unroll
            for (int ii = 0; ii < 2; ii++) {
                int i  = h * 2 + ii;                   // 0..3
                int kk = s + 8 * ii;                   // 0..15 within half

                const float4* F = (const float4*)(table + jj[i] * 12);
                float4 f0 = F[0], f1 = F[1], f2 = F[2];

                const float* P = rotbuf + g * ROT_STRIDE + kk * 9;
                const float* Q = trnbuf + g * TRN_STRIDE + kk * 3;

                float w = wgt[i];
                float R0x = f0.x, R0y = f0.y, R0z = f0.z;
                float R1x = f0.w, R1y = f1.x, R1z = f1.y;
                float R2x = f1.z, R2y = f1.w, R2z = f2.x;
                float tx  = f2.y, ty  = f2.z, tz  = f2.w;

#pragma unroll
                for (int c = 0; c < 3; c++) {
                    float p0 = P[c], p1 = P[3 + c], p2 = P[6 + c];
                    acc[0 + c] += w * (R0x * p0 + R0y * p1 + R0z * p2);
                    acc[3 + c] += w * (R1x * p0 + R1y * p1 + R1z * p2);
                    acc[6 + c] += w * (R2x * p0 + R2y * p1 + R2z * p2);
                }
                float q0 = Q[0], q1 = Q[1], q2 = Q[2];
                acc[9]  += w * (R0x * q0 + R0y * q1 + R0z * q2 + tx);
                acc[10] += w * (R1x * q0 + R1y * q1 + R1z * q2 + ty);
                acc[11] += w * (R2x * q0 + R2y * q1 + R2z * q2 + tz);
                acc[12] += w;
            }
            __syncwarp();
        }

        // --- butterfly reduce across the 8-lane group ---
#pragma unroll
        for (int v = 0; v < 13; v++) {
            acc[v] += __shfl_xor_sync(0xffffffffu, acc[v], 4);
            acc[v] += __shfl_xor_sync(0xffffffffu, acc[v], 2);
            acc[v] += __shfl_xor_sync(0xffffffffu, acc[v], 1);
        }

        if (s == 0) {
            float inv = __fdividef(1.0f, acc[12]);
            float4* o = (float4*)(g_avg + bng * 12);
            o[0] = make_float4(acc[0] * inv, acc[1] * inv, acc[2]  * inv, acc[3]  * inv);
            o[1] = make_float4(acc[4] * inv, acc[5] * inv, acc[6]  * inv, acc[7]  * inv);
            o[2] = make_float4(acc[8] * inv, acc[9] * inv, acc[10] * inv, acc[11] * inv);
        }
    }
}

// ---------------------------------------------------------------------------
// Kernel 2: one thread per (b,n). Jacobi SVD projection onto SO(3)
// (unchanged from the passing round-2/3 version).
// ---------------------------------------------------------------------------
template <int p, int q, int r>
__device__ __forceinline__ void jrot(float S[3][3], float V[3][3]) {
    float spq = S[p][q];
    if (fabsf(spq) > 1e-30f) {
        float tau = (S[q][q] - S[p][p]) / (2.0f * spq);
        float t   = copysignf(1.0f, tau) / (fabsf(tau) + sqrtf(1.0f + tau * tau));
        float c   = rsqrtf(1.0f + t * t);
        float s   = t * c;
        float spp = S[p][p], sqq = S[q][q];
        S[p][p] = spp - t * spq;
        S[q][q] = sqq + t * spq;
        S[p][q] = 0.0f; S[q][p] = 0.0f;
        float srp = S[r][p], srq = S[r][q];
        S[r][p] = c * srp - s * srq; S[p][r] = S[r][p];
        S[r][q] = s * srp + c * srq; S[q][r] = S[r][q];
#pragma unroll
        for (int i = 0; i < 3; i++) {
            float vip = V[i][p], viq = V[i][q];
            V[i][p] = c * vip - s * viq;
            V[i][q] = s * vip + c * viq;
        }
    }
}

__global__ __launch_bounds__(256) void svd_project_kernel(float* __restrict__ out) {
    int i = blockIdx.x * blockDim.x + threadIdx.x;
    if (i >= BN) return;

    const float4* m = (const float4*)(g_avg + (size_t)i * 12);
    float4 m0 = m[0], m1 = m[1], m2 = m[2];
    float a[3][3] = {{m0.x, m0.y, m0.z},
                     {m0.w, m1.x, m1.y},
                     {m1.z, m1.w, m2.x}};
    float t0 = m2.y, t1 = m2.z, t2 = m2.w;

    float S[3][3];
#pragma unroll
    for (int c = 0; c < 3; c++)
#pragma unroll
        for (int d = c; d < 3; d++) {
            float v = a[0][c] * a[0][d] + a[1][c] * a[1][d] + a[2][c] * a[2][d];
            S[c][d] = v; S[d][c] = v;
        }

    float V[3][3] = {{1, 0, 0}, {0, 1, 0}, {0, 0, 1}};
#pragma unroll
    for (int sweep = 0; sweep < 5; sweep++) {
        jrot<0, 1, 2>(S, V);
        jrot<0, 2, 1>(S, V);
        jrot<1, 2, 0>(S, V);
    }

    float l0 = S[0][0], l1 = S[1][1], l2 = S[2][2];
    float v0x = V[0][0], v0y = V[1][0], v0z = V[2][0];
    float v1x = V[0][1], v1y = V[1][1], v1z = V[2][1];
    float v2x = V[0][2], v2y = V[1][2], v2z = V[2][2];

#define CSWAP(la, lb, ax, ay, az, bx, by, bz)                                  \
    if (la < lb) {                                                             \
        float tmp;                                                             \
        tmp = la; la = lb; lb = tmp;                                           \
        tmp = ax; ax = bx; bx = tmp;                                           \
        tmp = ay; ay = by; by = tmp;                                           \
        tmp = az; az = bz; bz = tmp;                                           \
    }
    CSWAP(l0, l1, v0x, v0y, v0z, v1x, v1y, v1z)
    CSWAP(l0, l2, v0x, v0y, v0z, v2x, v2y, v2z)
    CSWAP(l1, l2, v1x, v1y, v1z, v2x, v2y, v2z)
#undef CSWAP

    float cx = v1y * v2z - v1z * v2y;
    float cy = v1z * v2x - v1x * v2z;
    float cz = v1x * v2y - v1y * v2x;
    float det = v0x * cx + v0y * cy + v0z * cz;
    if (det < 0.0f) { v2x = -v2x; v2y = -v2y; v2z = -v2z; }

    float u0x = a[0][0] * v0x + a[0][1] * v0y + a[0][2] * v0z;
    float u0y = a[1][0] * v0x + a[1][1] * v0y + a[1][2] * v0z;
    float u0z = a[2][0] * v0x + a[2][1] * v0y + a[2][2] * v0z;
    float inv0 = rsqrtf(u0x * u0x + u0y * u0y + u0z * u0z + 1e-30f);
    u0x *= inv0; u0y *= inv0; u0z *= inv0;

    float u1x = a[0][0] * v1x + a[0][1] * v1y + a[0][2] * v1z;
    float u1y = a[1][0] * v1x + a[1][1] * v1y + a[1][2] * v1z;
    float u1z = a[2][0] * v1x + a[2][1] * v1y + a[2][2] * v1z;
    float dp = u0x * u1x + u0y * u1y + u0z * u1z;
    u1x -= dp * u0x; u1y -= dp * u0y; u1z -= dp * u0z;
    float inv1 = rsqrtf(u1x * u1x + u1y * u1y + u1z * u1z + 1e-30f);
    u1x *= inv1; u1y *= inv1; u1z *= inv1;

    float u2x = u0y * u1z - u0z * u1y;
    float u2y = u0z * u1x - u0x * u1z;
    float u2z = u0x * u1y - u0y * u1x;

    float R00 = u0x * v0x + u1x * v1x + u2x * v2x;
    float R01 = u0x * v0y + u1x * v1y + u2x * v2y;
    float R02 = u0x * v0z + u1x * v1z + u2x * v2z;
    float R10 = u0y * v0x + u1y * v1x + u2y * v2x;
    float R11 = u0y * v0y + u1y * v1y + u2y * v2y;
    float R12 = u0y * v0z + u1y * v1z + u2y * v2z;
    float R20 = u0z * v0x + u1z * v1x + u2z * v2x;
    float R21 = u0z * v0y + u1z * v1y + u2z * v2y;
    float R22 = u0z * v0z + u1z * v1z + u2z * v2z;

    float4* o = (float4*)(out + (size_t)i * 12);
    o[0] = make_float4(R00, R01, R02, R10);
    o[1] = make_float4(R11, R12, R20, R21);
    o[2] = make_float4(R22, t0, t1, t2);
}

// ---------------------------------------------------------------------------
extern "C" void kernel_launch(void* const* d_in, const int* in_sizes, int n_in,
                              void* d_out, int out_size) {
    const float* frames_rot   = (const float*)d_in[0];
    const float* frames_trans = (const float*)d_in[1];
    const float* pair_rot     = (const float*)d_in[2];
    const float* pair_trans   = (const float*)d_in[3];
    const float* confidences  = (const float*)d_in[4];
    const int*   topology     = (const int*)d_in[5];
    float*       out          = (float*)d_out;

    cudaFuncSetAttribute(compose_avg_kernel,
                         cudaFuncAttributeMaxDynamicSharedMemorySize, SMEM_BYTES);

    compose_avg_kernel<<<B * BLOCKS_PER_BATCH, THREADS, SMEM_BYTES>>>(
        frames_rot, frames_trans, pair_rot, pair_trans, confidences, topology);

    svd_project_kernel<<<BN / 256, 256>>>(out);
}

// round 5
// speedup vs baseline: 1.3020x; 1.3020x over previous
#include <cuda_runtime.h>

// Problem constants (fixed shapes)
constexpr int B  = 16;
constexpr int N  = 4096;
constexpr int K  = 32;
constexpr int BN = B * N;   // 65536

// compose kernel geometry
constexpr int TSR = 296;                  // rot tile stride (floats), %32==8 -> conflict-free
constexpr int TST = 104;                  // trans tile stride (floats), %32==8
constexpr int WSM = 4 * TSR + 4 * TST;    // 1600 floats per warp staging
constexpr int CWARPS   = 16;
constexpr int CTHREADS = CWARPS * 32;     // 512
constexpr int NCHUNK   = BN / 32;         // 2048 chunks of 32 bn
constexpr int CSMEM    = CWARPS * WSM * 4; // 102400 B

// packed frames [rot 9 | trans 3] per (b,n), 48B rows
__device__ float g_frames[BN * 12];

// ---------------------------------------------------------------------------
// Kernel 1: repack frames into 48-byte rows. Fully coalesced float4 global
// loads -> smem transpose -> STG.128 writes. 256 frames per block.
// ---------------------------------------------------------------------------
__global__ __launch_bounds__(256) void repack_frames_kernel(
    const float* __restrict__ fr, const float* __restrict__ ft) {
    __shared__ __align__(16) float s[256 * 12];
    int t = threadIdx.x;
    int blk = blockIdx.x;

    const float4* fr4 = (const float4*)fr + (size_t)blk * 576;  // 256*9/4
#pragma unroll
    for (int q = 0; q < 2; q++) {
        float4 v = fr4[q * 256 + t];
        int e = (q * 256 + t) * 4;
#pragma unroll
        for (int u = 0; u < 4; u++) {
            int el = e + u;
            int fi = el / 9, c = el - fi * 9;
            s[fi * 12 + c] = (&v.x)[u];
        }
    }
    if (t < 64) {
        float4 v = fr4[512 + t];
        int e = (512 + t) * 4;
#pragma unroll
        for (int u = 0; u < 4; u++) {
            int el = e + u;
            int fi = el / 9, c = el - fi * 9;
            s[fi * 12 + c] = (&v.x)[u];
        }
    }
    const float4* ft4 = (const float4*)ft + (size_t)blk * 192;  // 256*3/4
    if (t < 192) {
        float4 v = ft4[t];
        int e = t * 4;
#pragma unroll
        for (int u = 0; u < 4; u++) {
            int el = e + u;
            int fi = el / 3, c = el - fi * 3;
            s[fi * 12 + 9 + c] = (&v.x)[u];
        }
    }
    __syncthreads();

    const float4* row = (const float4*)(s + t * 12);
    float4* o = (float4*)g_frames + ((size_t)blk * 256 + t) * 3;
    o[0] = row[0]; o[1] = row[1]; o[2] = row[2];
}

// ---------------------------------------------------------------------------
// SO(3) projection (Jacobi eigendecomposition of A^T A), per-thread.
// ---------------------------------------------------------------------------
template <int p, int q, int r>
__device__ __forceinline__ void jrot(float S[3][3], float V[3][3]) {
    float spq = S[p][q];
    if (fabsf(spq) > 1e-30f) {
        float tau = (S[q][q] - S[p][p]) / (2.0f * spq);
        float t   = copysignf(1.0f, tau) / (fabsf(tau) + sqrtf(1.0f + tau * tau));
        float c   = rsqrtf(1.0f + t * t);
        float sn  = t * c;
        float spp = S[p][p], sqq = S[q][q];
        S[p][p] = spp - t * spq;
        S[q][q] = sqq + t * spq;
        S[p][q] = 0.0f; S[q][p] = 0.0f;
        float srp = S[r][p], srq = S[r][q];
        S[r][p] = c * srp - sn * srq; S[p][r] = S[r][p];
        S[r][q] = sn * srp + c * srq; S[q][r] = S[r][q];
#pragma unroll
        for (int i = 0; i < 3; i++) {
            float vip = V[i][p], viq = V[i][q];
            V[i][p] = c * vip - sn * viq;
            V[i][q] = sn * vip + c * viq;
        }
    }
}

__device__ __forceinline__ void svd_project_write(const float* stash, float4* o) {
    // rot part: SVD is invariant to positive scaling, use unnormalized sums
    float a[3][3] = {{stash[0], stash[1], stash[2]},
                     {stash[3], stash[4], stash[5]},
                     {stash[6], stash[7], stash[8]}};
    float inv = __fdividef(1.0f, stash[12]);
    float t0 = stash[9] * inv, t1 = stash[10] * inv, t2 = stash[11] * inv;

    float S[3][3];
#pragma unroll
    for (int c = 0; c < 3; c++)
#pragma unroll
        for (int d = c; d < 3; d++) {
            float v = a[0][c] * a[0][d] + a[1][c] * a[1][d] + a[2][c] * a[2][d];
            S[c][d] = v; S[d][c] = v;
        }

    float V[3][3] = {{1, 0, 0}, {0, 1, 0}, {0, 0, 1}};
#pragma unroll
    for (int sweep = 0; sweep < 5; sweep++) {
        jrot<0, 1, 2>(S, V);
        jrot<0, 2, 1>(S, V);
        jrot<1, 2, 0>(S, V);
    }

    float l0 = S[0][0], l1 = S[1][1], l2 = S[2][2];
    float v0x = V[0][0], v0y = V[1][0], v0z = V[2][0];
    float v1x = V[0][1], v1y = V[1][1], v1z = V[2][1];
    float v2x = V[0][2], v2y = V[1][2], v2z = V[2][2];

#define CSWAP(la, lb, ax, ay, az, bx, by, bz)                                  \
    if (la < lb) {                                                             \
        float tmp;                                                             \
        tmp = la; la = lb; lb = tmp;                                           \
        tmp = ax; ax = bx; bx = tmp;                                           \
        tmp = ay; ay = by; by = tmp;                                           \
        tmp = az; az = bz; bz = tmp;                                           \
    }
    CSWAP(l0, l1, v0x, v0y, v0z, v1x, v1y, v1z)
    CSWAP(l0, l2, v0x, v0y, v0z, v2x, v2y, v2z)
    CSWAP(l1, l2, v1x, v1y, v1z, v2x, v2y, v2z)
#undef CSWAP

    float cx = v1y * v2z - v1z * v2y;
    float cy = v1z * v2x - v1x * v2z;
    float cz = v1x * v2y - v1y * v2x;
    float det = v0x * cx + v0y * cy + v0z * cz;
    if (det < 0.0f) { v2x = -v2x; v2y = -v2y; v2z = -v2z; }

    float u0x = a[0][0] * v0x + a[0][1] * v0y + a[0][2] * v0z;
    float u0y = a[1][0] * v0x + a[1][1] * v0y + a[1][2] * v0z;
    float u0z = a[2][0] * v0x + a[2][1] * v0y + a[2][2] * v0z;
    float inv0 = rsqrtf(u0x * u0x + u0y * u0y + u0z * u0z + 1e-30f);
    u0x *= inv0; u0y *= inv0; u0z *= inv0;

    float u1x = a[0][0] * v1x + a[0][1] * v1y + a[0][2] * v1z;
    float u1y = a[1][0] * v1x + a[1][1] * v1y + a[1][2] * v1z;
    float u1z = a[2][0] * v1x + a[2][1] * v1y + a[2][2] * v1z;
    float dp = u0x * u1x + u0y * u1y + u0z * u1z;
    u1x -= dp * u0x; u1y -= dp * u0y; u1z -= dp * u0z;
    float inv1 = rsqrtf(u1x * u1x + u1y * u1y + u1z * u1z + 1e-30f);
    u1x *= inv1; u1y *= inv1; u1z *= inv1;

    float u2x = u0y * u1z - u0z * u1y;
    float u2y = u0z * u1x - u0x * u1z;
    float u2z = u0x * u1y - u0y * u1x;

    float R00 = u0x * v0x + u1x * v1x + u2x * v2x;
    float R01 = u0x * v0y + u1x * v1y + u2x * v2y;
    float R02 = u0x * v0z + u1x * v1z + u2x * v2z;
    float R10 = u0y * v0x + u1y * v1x + u2y * v2x;
    float R11 = u0y * v0y + u1y * v1y + u2y * v2y;
    float R12 = u0y * v0z + u1y * v1z + u2y * v2z;
    float R20 = u0z * v0x + u1z * v1x + u2z * v2x;
    float R21 = u0z * v0y + u1z * v1y + u2z * v2y;
    float R22 = u0z * v0z + u1z * v1z + u2z * v2z;

    o[0] = make_float4(R00, R01, R02, R10);
    o[1] = make_float4(R11, R12, R20, R21);
    o[2] = make_float4(R22, t0, t1, t2);
}

// ---------------------------------------------------------------------------
// Kernel 2 (compose + average + SVD, fused):
// grid = 148 blocks x 16 warps; warp handles chunk = blockIdx + 148*warp
// (32 consecutive bn, 8 iterations of 4 bn). After each iteration's 8-lane
// butterfly reduce, results are stashed onto lanes it*4+g; the epilogue runs
// 32 fully-parallel SVDs and writes the output directly.
// ---------------------------------------------------------------------------
__global__ __launch_bounds__(CTHREADS) void compose_svd_kernel(
    const float* __restrict__ pair_rot,
    const float* __restrict__ pair_trans,
    const float* __restrict__ conf,
    const int*   __restrict__ topo,
    float*       __restrict__ out) {

    extern __shared__ float sm[];
    int tid  = threadIdx.x;
    int warp = tid >> 5;
    int lane = tid & 31;
    int g    = lane >> 3;
    int s    = lane & 7;

    int chunk = blockIdx.x + 148 * warp;   // balanced: every SM ~13-14 chunks
    if (chunk >= NCHUNK) return;           // no __syncthreads below -> safe

    int b = chunk >> 7;                    // 128 chunks per batch
    const float* fbase = g_frames + (size_t)(b << 12) * 12;

    float* rotbuf = sm + warp * WSM;
    float* trnbuf = rotbuf + 4 * TSR;
    float4* rb4 = (float4*)rotbuf;         // tile stride 74 float4
    float4* tb4 = (float4*)trnbuf;         // tile stride 26 float4

    const float4* pr4 = (const float4*)pair_rot;
    const float4* pt4 = (const float4*)pair_trans;

    size_t chunkbn = (size_t)chunk * 32;
    float stash[13];

    for (int it = 0; it < 8; it++) {
        size_t bn0 = chunkbn + it * 4;
        size_t bng = bn0 + g;

        // --- conf & topo for this lane's 4 neighbors ---
        const float* cfb = conf + bng * K;
        const int*   tpb = topo + bng * K;
        float wgt[4];
        int   jj[4];
#pragma unroll
        for (int i = 0; i < 4; i++) {
            wgt[i] = cfb[s + 8 * i];
            jj[i]  = tpb[s + 8 * i];
        }

        // --- issue random frame gathers early (12 independent LDG.128) ---
        float4 F[4][3];
#pragma unroll
        for (int i = 0; i < 4; i++) {
            const float4* Fp = (const float4*)(fbase + (size_t)jj[i] * 12);
            F[i][0] = Fp[0]; F[i][1] = Fp[1]; F[i][2] = Fp[2];
        }

        // --- stage pair tiles (coalesced float4 loads, padded smem) ---
#pragma unroll
        for (int q = 0; q < 9; q++) {
            int f = q * 32 + lane;             // 0..287
            int t = f / 72, w = f - t * 72;
            rb4[t * 74 + w] = pr4[bn0 * 72 + f];
        }
#pragma unroll
        for (int q = 0; q < 3; q++) {
            int f = q * 32 + lane;             // 0..95
            int t = f / 24, w = f - t * 24;
            tb4[t * 26 + w] = pt4[bn0 * 24 + f];
        }
        __syncwarp();

        float acc[13];
#pragma unroll
        for (int v = 0; v < 13; v++) acc[v] = 0.0f;

#pragma unroll
        for (int i = 0; i < 4; i++) {
            int k = s + 8 * i;
            const float* P = rotbuf + g * TSR + k * 9;   // conflict-free LDS
            const float* Q = trnbuf + g * TST + k * 3;

            float w = wgt[i];
            float R0x = F[i][0].x, R0y = F[i][0].y, R0z = F[i][0].z;
            float R1x = F[i][0].w, R1y = F[i][1].x, R1z = F[i][1].y;
            float R2x = F[i][1].z, R2y = F[i][1].w, R2z = F[i][2].x;
            float tx  = F[i][2].y, ty  = F[i][2].z, tz  = F[i][2].w;

#pragma unroll
            for (int c = 0; c < 3; c++) {
                float p0 = P[c], p1 = P[3 + c], p2 = P[6 + c];
                acc[0 + c] += w * (R0x * p0 + R0y * p1 + R0z * p2);
                acc[3 + c] += w * (R1x * p0 + R1y * p1 + R1z * p2);
                acc[6 + c] += w * (R2x * p0 + R2y * p1 + R2z * p2);
            }
            float q0 = Q[0], q1 = Q[1], q2 = Q[2];
            acc[9]  += w * (R0x * q0 + R0y * q1 + R0z * q2 + tx);
            acc[10] += w * (R1x * q0 + R1y * q1 + R1z * q2 + ty);
            acc[11] += w * (R2x * q0 + R2y * q1 + R2z * q2 + tz);
            acc[12] += w;
        }
        __syncwarp();   // staging buffer reused next iteration

        // --- butterfly reduce within 8-lane groups (result in all lanes) ---
#pragma unroll
        for (int v = 0; v < 13; v++) {
            acc[v] += __shfl_xor_sync(0xffffffffu, acc[v], 4);
            acc[v] += __shfl_xor_sync(0xffffffffu, acc[v], 2);
            acc[v] += __shfl_xor_sync(0xffffffffu, acc[v], 1);
        }

        // --- stash: lane L = it*4 + g' collects group g' of iteration it ---
        int src = (lane & 3) * 8;
#pragma unroll
        for (int v = 0; v < 13; v++) {
            float tmp = __shfl_sync(0xffffffffu, acc[v], src);
            if ((lane >> 2) == it) stash[v] = tmp;
        }
    }

    // --- epilogue: 32 fully-parallel SVDs, one bn per lane ---
    float4* o = (float4*)out + (chunkbn + lane) * 3;
    svd_project_write(stash, o);
}

// ---------------------------------------------------------------------------
extern "C" void kernel_launch(void* const* d_in, const int* in_sizes, int n_in,
                              void* d_out, int out_size) {
    const float* frames_rot   = (const float*)d_in[0];
    const float* frames_trans = (const float*)d_in[1];
    const float* pair_rot     = (const float*)d_in[2];
    const float* pair_trans   = (const float*)d_in[3];
    const float* confidences  = (const float*)d_in[4];
    const int*   topology     = (const int*)d_in[5];
    float*       out          = (float*)d_out;

    cudaFuncSetAttribute(compose_svd_kernel,
                         cudaFuncAttributeMaxDynamicSharedMemorySize, CSMEM);

    repack_frames_kernel<<<BN / 256, 256>>>(frames_rot, frames_trans);
    compose_svd_kernel<<<148, CTHREADS, CSMEM>>>(pair_rot, pair_trans,
                                                 confidences, topology, out);
}